// round 1
// baseline (speedup 1.0000x reference)
#include <cuda_runtime.h>
#include <math.h>

// SSIM loss: pred/target [16,3,512,512] f32, window [3,1,11,11] (Gaussian outer product).
// Separable depthwise conv of {p, t, p^2, t^2, p*t} + pointwise SSIM + global mean.

#define TILE   32
#define HALO   5
#define KW     11
#define TW     (TILE + 2*HALO)   // 42
#define IMG_H  512
#define IMG_W  512
#define NCHAN  48                // 16 * 3
#define NTHREADS 256

#define C1F 1.0e-4f
#define C2F 9.0e-4f

__device__ double g_accum;

__global__ void init_kernel() { g_accum = 0.0; }

__global__ __launch_bounds__(NTHREADS) void ssim_kernel(
    const float* __restrict__ pred,
    const float* __restrict__ target,
    const float* __restrict__ window)
{
    __shared__ float sp[TW][TW];
    __shared__ float st[TW][TW];
    __shared__ float hm1[TW][TILE];
    __shared__ float hm2[TW][TILE];
    __shared__ float hpp[TW][TILE];
    __shared__ float htt[TW][TILE];
    __shared__ float hpt[TW][TILE];
    __shared__ float sg[KW];
    __shared__ float warp_sums[8];

    const int tid = threadIdx.x;

    // Recover 1D Gaussian taps from the 2D outer-product window: g[i] = sqrt(w[i][i]).
    if (tid < KW) sg[tid] = sqrtf(window[tid * KW + tid]);

    const int x0 = blockIdx.x * TILE - HALO;
    const int y0 = blockIdx.y * TILE - HALO;
    const size_t plane = (size_t)blockIdx.z * (IMG_H * IMG_W);
    const float* __restrict__ pbase = pred + plane;
    const float* __restrict__ tbase = target + plane;

    // ---- Load 42x42 halo tile (zero-padded) ----
    #pragma unroll
    for (int i = tid; i < TW * TW; i += NTHREADS) {
        int ly = i / TW, lx = i - ly * TW;
        int gx = x0 + lx, gy = y0 + ly;
        float p = 0.f, t = 0.f;
        if ((unsigned)gx < IMG_W && (unsigned)gy < IMG_H) {
            int off = gy * IMG_W + gx;
            p = pbase[off];
            t = tbase[off];
        }
        sp[ly][lx] = p;
        st[ly][lx] = t;
    }
    __syncthreads();

    float g[KW];
    #pragma unroll
    for (int k = 0; k < KW; k++) g[k] = sg[k];

    // ---- Horizontal pass: 42 rows x 32 cols, groups of 4 adjacent outputs ----
    // 42*8 = 336 groups; each group reads 14 input columns, emits 4 outputs x 5 arrays.
    for (int grp = tid; grp < TW * 8; grp += NTHREADS) {
        int row = grp >> 3;
        int xg  = (grp & 7) << 2;

        float am1[4] = {0.f,0.f,0.f,0.f};
        float am2[4] = {0.f,0.f,0.f,0.f};
        float app[4] = {0.f,0.f,0.f,0.f};
        float att[4] = {0.f,0.f,0.f,0.f};
        float apt[4] = {0.f,0.f,0.f,0.f};

        #pragma unroll
        for (int k = 0; k < KW + 3; k++) {
            float p = sp[row][xg + k];
            float t = st[row][xg + k];
            float pp = p * p, tt = t * t, pt = p * t;
            #pragma unroll
            for (int o = 0; o < 4; o++) {
                int ki = k - o;
                if (ki >= 0 && ki < KW) {
                    float w = g[ki];
                    am1[o] = fmaf(w, p,  am1[o]);
                    am2[o] = fmaf(w, t,  am2[o]);
                    app[o] = fmaf(w, pp, app[o]);
                    att[o] = fmaf(w, tt, att[o]);
                    apt[o] = fmaf(w, pt, apt[o]);
                }
            }
        }
        *(float4*)&hm1[row][xg] = make_float4(am1[0], am1[1], am1[2], am1[3]);
        *(float4*)&hm2[row][xg] = make_float4(am2[0], am2[1], am2[2], am2[3]);
        *(float4*)&hpp[row][xg] = make_float4(app[0], app[1], app[2], app[3]);
        *(float4*)&htt[row][xg] = make_float4(att[0], att[1], att[2], att[3]);
        *(float4*)&hpt[row][xg] = make_float4(apt[0], apt[1], apt[2], apt[3]);
    }
    __syncthreads();

    // ---- Vertical pass: each thread owns one x column, 4 consecutive y outputs ----
    const int tx   = tid & 31;
    const int tyg  = tid >> 5;        // 0..7
    const int ybase = tyg << 2;       // 0,4,...,28

    float vm1[4] = {0.f,0.f,0.f,0.f};
    float vm2[4] = {0.f,0.f,0.f,0.f};
    float vpp[4] = {0.f,0.f,0.f,0.f};
    float vtt[4] = {0.f,0.f,0.f,0.f};
    float vpt[4] = {0.f,0.f,0.f,0.f};

    #pragma unroll
    for (int k = 0; k < KW + 3; k++) {
        int row = ybase + k;
        float a = hm1[row][tx];
        float b = hm2[row][tx];
        float c = hpp[row][tx];
        float d = htt[row][tx];
        float e = hpt[row][tx];
        #pragma unroll
        for (int o = 0; o < 4; o++) {
            int ki = k - o;
            if (ki >= 0 && ki < KW) {
                float w = g[ki];
                vm1[o] = fmaf(w, a, vm1[o]);
                vm2[o] = fmaf(w, b, vm2[o]);
                vpp[o] = fmaf(w, c, vpp[o]);
                vtt[o] = fmaf(w, d, vtt[o]);
                vpt[o] = fmaf(w, e, vpt[o]);
            }
        }
    }

    // ---- SSIM map + local accumulation ----
    float lsum = 0.f;
    #pragma unroll
    for (int o = 0; o < 4; o++) {
        float mu1 = vm1[o], mu2 = vm2[o];
        float mu1s = mu1 * mu1;
        float mu2s = mu2 * mu2;
        float mu12 = mu1 * mu2;
        float s1  = vpp[o] - mu1s;
        float s2  = vtt[o] - mu2s;
        float s12 = vpt[o] - mu12;
        float num = (2.f * mu12 + C1F) * (2.f * s12 + C2F);
        float den = (mu1s + mu2s + C1F) * (s1 + s2 + C2F);
        lsum += __fdividef(num, den);
    }

    // ---- Block reduce + global atomic ----
    #pragma unroll
    for (int off = 16; off > 0; off >>= 1)
        lsum += __shfl_down_sync(0xffffffffu, lsum, off);
    if (tx == 0) warp_sums[tyg] = lsum;
    __syncthreads();
    if (tid == 0) {
        float s = 0.f;
        #pragma unroll
        for (int i = 0; i < 8; i++) s += warp_sums[i];
        atomicAdd(&g_accum, (double)s);
    }
}

__global__ void finalize_kernel(float* __restrict__ out) {
    const double n = (double)NCHAN * IMG_H * IMG_W;
    out[0] = (float)(1.0 - g_accum / n);
}

extern "C" void kernel_launch(void* const* d_in, const int* in_sizes, int n_in,
                              void* d_out, int out_size)
{
    const float* pred   = (const float*)d_in[0];
    const float* target = (const float*)d_in[1];
    const float* window = (const float*)d_in[2];
    float* out = (float*)d_out;

    init_kernel<<<1, 1>>>();
    dim3 grid(IMG_W / TILE, IMG_H / TILE, NCHAN);
    ssim_kernel<<<grid, NTHREADS>>>(pred, target, window);
    finalize_kernel<<<1, 1>>>(out);
}